// round 5
// baseline (speedup 1.0000x reference)
#include <cuda_runtime.h>

#define W    512
#define H    512
#define CH   8            // rows per chunk
#define NCH  64           // chunks per column
#define CPB  4            // columns per block
#define TPB  256          // CPB * NCH
#define NBLK 256          // 2 images * (512 / CPB)
#define BIG  (1 << 20)

__device__ double   g_sum[NBLK][2];
__device__ unsigned g_cnt[NBLK][2];
__device__ unsigned g_ctr;

__global__ __launch_bounds__(TPB) void morph_all(const float* __restrict__ img,
                                                 const float* __restrict__ mask,
                                                 const float* __restrict__ tgt,
                                                 float* __restrict__ out) {
    __shared__ float    lut[1025];
    __shared__ unsigned LA[TPB], MB[TPB];     // packed (fg<<16 | bg)
    __shared__ unsigned CP[TPB], UP[TPB];     // packed carries
    __shared__ int      xAf[CPB], xAb[CPB], xBf[CPB], xBb[CPB];
    __shared__ double   wsum[8][2];
    __shared__ unsigned wcnt[8][2];
    __shared__ int      isLast;
    __shared__ double   fsum[4];
    __shared__ unsigned fcnt[4];

    const int tid = threadIdx.x;
    for (int v = tid; v < 1025; v += TPB)
        lut[v] = (v == 1024) ? 1024.0f
                             : __fsqrt_rn((float)(v * v + (v & 1)) * 0.5f);

    const int b     = blockIdx.x;
    const int im    = b >> 7;                  // 0 = img, 1 = target
    const int cloc  = tid & (CPB - 1);
    const int chunk = tid >> 2;
    const int col   = ((b & 127) << 2) + cloc;
    const int rowBase = chunk * CH;

    const float* ps = (im ? tgt : img) + (size_t)rowBase * W + col;
    const float* pm = mask              + (size_t)rowBase * W + col;

    // ---- phase 1: local forward scan, register state ----
    int      lf[CH];
    unsigned bbits = 0u, mbits = 0u;
    int dfg = 1024, dbg = 1024, p = CH;
    bool ph0 = false;
#pragma unroll
    for (int j = 0; j < CH; j++) {
        bool bb = ps[j * W] > 0.22f;
        bool mm = pm[j * W] > 0.5f;
        bbits |= bb ? (1u << j) : 0u;
        mbits |= mm ? (1u << j) : 0u;
        if (j == 0) ph0 = bb;
        else if (p == CH && bb != ph0) p = j;
        dfg = bb ? dfg + 1 : 0;          // <= 1032, fits u16
        dbg = bb ? 0 : dbg + 1;
        lf[j] = bb ? dfg : dbg;
    }
    int Mfg = ph0 ? ((p < CH) ? p : 1024) : 0;
    int Mbg = ph0 ? 0 : ((p < CH) ? p : 1024);
    LA[tid] = ((unsigned)dfg << 16) | (unsigned)dbg;
    MB[tid] = ((unsigned)Mfg << 16) | (unsigned)Mbg;
    __syncthreads();

    // ---- carry scan (role remap): column = tid>>6, chunk = tid&63 ----
    {
        const int lane  = tid & 31;
        const int hi    = (tid >> 5) & 1;       // upper 32 chunks of the column
        const int s_chk = tid & 63;
        const int s_col = tid >> 6;

        unsigned Lp = LA[s_chk * CPB + s_col];
        unsigned Mp = MB[s_chk * CPB + s_col];
        int Af = (int)(Lp >> 16)      - CH * s_chk;
        int Ab = (int)(Lp & 0xFFFFu)  - CH * s_chk;
        int Bf = (int)(Mp >> 16)      + CH * s_chk;
        int Bb = (int)(Mp & 0xFFFFu)  + CH * s_chk;

        int iAf = Af, iAb = Ab, iBf = Bf, iBb = Bb;
#pragma unroll
        for (int d = 1; d < 32; d <<= 1) {
            int ta = __shfl_up_sync(0xFFFFFFFFu, iAf, d);
            int tb = __shfl_up_sync(0xFFFFFFFFu, iAb, d);
            if (lane >= d) { iAf = min(iAf, ta); iAb = min(iAb, tb); }
            int tc = __shfl_down_sync(0xFFFFFFFFu, iBf, d);
            int td = __shfl_down_sync(0xFFFFFFFFu, iBb, d);
            if (lane < 32 - d) { iBf = min(iBf, tc); iBb = min(iBb, td); }
        }
        if (!hi && lane == 31) { xAf[s_col] = iAf; xAb[s_col] = iAb; }
        if ( hi && lane == 0 ) { xBf[s_col] = iBf; xBb[s_col] = iBb; }
        __syncthreads();

        // forward exclusive prefix-min (with lower-warp total folded in)
        int mAf = hi ? min(iAf, xAf[s_col]) : iAf;
        int mAb = hi ? min(iAb, xAb[s_col]) : iAb;
        int eAf = __shfl_up_sync(0xFFFFFFFFu, mAf, 1);
        int eAb = __shfl_up_sync(0xFFFFFFFFu, mAb, 1);
        if (lane == 0) { eAf = hi ? xAf[s_col] : BIG; eAb = hi ? xAb[s_col] : BIG; }
        // backward exclusive suffix-min (with upper-warp total folded in)
        int mBf = hi ? iBf : min(iBf, xBf[s_col]);
        int mBb = hi ? iBb : min(iBb, xBb[s_col]);
        int eBf = __shfl_down_sync(0xFFFFFFFFu, mBf, 1);
        int eBb = __shfl_down_sync(0xFFFFFFFFu, mBb, 1);
        if (lane == 31) { eBf = hi ? BIG : xBf[s_col]; eBb = hi ? BIG : xBb[s_col]; }

        int cfg = min(eAf + CH * (s_chk - 1), 1024);
        int cbg = min(eAb + CH * (s_chk - 1), 1024);
        int ufg = min(eBf - CH * (s_chk + 1), 1024);
        int ubg = min(eBb - CH * (s_chk + 1), 1024);
        CP[s_chk * CPB + s_col] = ((unsigned)cfg << 16) | (unsigned)cbg;
        UP[s_chk * CPB + s_col] = ((unsigned)ufg << 16) | (unsigned)ubg;
    }
    __syncthreads();

    unsigned cp = CP[tid], up = UP[tid];
    int cfg = (int)(cp >> 16), cbg = (int)(cp & 0xFFFFu);
    int ufg = (int)(up >> 16), ubg = (int)(up & 0xFFFFu);

    // ---- phase 2: backward scan + combine + accumulate ----
    float    sfg = 0.0f, sbg = 0.0f;
    unsigned nfg = 0u,   nbg = 0u;
#pragma unroll
    for (int j = CH - 1; j >= 0; j--) {
        bool bb = (bbits >> j) & 1u;
        ufg = bb ? ufg + 1 : 0;
        ubg = bb ? 0 : ubg + 1;
        int ef  = min(lf[j], (bb ? cfg : cbg) + j + 1);
        int eb  = bb ? ufg : ubg;
        int idx = min(min(ef, eb), 1024);
        float d = lut[idx];
        bool mm = (mbits >> j) & 1u;
        if (mm &&  bb) { sfg += d; nfg++; }
        if (mm && !bb) { sbg += d; nbg++; }
    }

    // ---- warp shfl reduction, then cross-warp ----
#pragma unroll
    for (int o = 16; o > 0; o >>= 1) {
        sfg += __shfl_down_sync(0xFFFFFFFFu, sfg, o);
        sbg += __shfl_down_sync(0xFFFFFFFFu, sbg, o);
        nfg += __shfl_down_sync(0xFFFFFFFFu, nfg, o);
        nbg += __shfl_down_sync(0xFFFFFFFFu, nbg, o);
    }
    const int wid = tid >> 5, lid = tid & 31;
    if (lid == 0) {
        wsum[wid][0] = (double)sfg;  wsum[wid][1] = (double)sbg;
        wcnt[wid][0] = nfg;          wcnt[wid][1] = nbg;
    }
    __syncthreads();
    if (tid == 0) {
        double   s0 = 0.0, s1 = 0.0;
        unsigned c0 = 0u,  c1 = 0u;
#pragma unroll
        for (int k = 0; k < 8; k++) {
            s0 += wsum[k][0];  s1 += wsum[k][1];
            c0 += wcnt[k][0];  c1 += wcnt[k][1];
        }
        g_sum[b][0] = s0;  g_sum[b][1] = s1;
        g_cnt[b][0] = c0;  g_cnt[b][1] = c1;
        __threadfence();
        isLast = (atomicAdd(&g_ctr, 1u) == NBLK - 1);
    }
    __syncthreads();

    // ---- last block: parallel deterministic final reduction + loss ----
    if (isLast) {
        if (tid < 128) {
            int ph = tid >> 5, ln = tid & 31;   // 4 phases x 32 lanes
            int base = (ph >> 1) * 128;
            int e    = ph & 1;
            double   s = 0.0;
            unsigned c = 0u;
#pragma unroll
            for (int t = 0; t < 4; t++) {
                int k = base + ln + 32 * t;
                s += g_sum[k][e];
                c += g_cnt[k][e];
            }
#pragma unroll
            for (int o = 16; o > 0; o >>= 1) {
                s += __shfl_down_sync(0xFFFFFFFFu, s, o);
                c += __shfl_down_sync(0xFFFFFFFFu, c, o);
            }
            if (ln == 0) { fsum[ph] = s; fcnt[ph] = c; }
        }
        __syncthreads();
        if (tid == 0) {
            const double VX2   = 21.0;
            const double TH_MU = 48.7578, TH_SD = 5.2874;
            const double SP_MU = 156.729, SP_SD = 46.1809;
            double n0 = fcnt[0] ? (double)fcnt[0] : 1.0;
            double n1 = fcnt[1] ? (double)fcnt[1] : 1.0;
            double n2 = fcnt[2] ? (double)fcnt[2] : 1.0;
            double n3 = fcnt[3] ? (double)fcnt[3] : 1.0;
            double tl = VX2 * fsum[0] / n0;
            double sl = VX2 * fsum[1] / n1;
            double th = VX2 * fsum[2] / n2;
            double sh = VX2 * fsum[3] / n3;
            double l1 = (tl - TH_MU) / TH_SD - (th - TH_MU) / TH_SD;
            double l7 = (sl - SP_MU) / SP_SD - (sh - SP_MU) / SP_SD;
            out[0] = (float)(0.5 * (l1 * l1 + l7 * l7));
            g_ctr = 0;
        }
    }
}

extern "C" void kernel_launch(void* const* d_in, const int* in_sizes, int n_in,
                              void* d_out, int out_size) {
    const float* img  = (const float*)d_in[0];
    const float* mask = (const float*)d_in[1];
    const float* tgt  = (const float*)d_in[2];
    morph_all<<<NBLK, TPB>>>(img, mask, tgt, (float*)d_out);
}

// round 7
// speedup vs baseline: 1.3570x; 1.3570x over previous
#include <cuda_runtime.h>

#define W    512
#define H    512
#define CH   16           // rows per chunk
#define NCH  32           // chunks per column
#define CPB  4            // columns per block
#define TPB  128          // CPB * NCH
#define NBLK 256          // 2 images * (512 / CPB)

__device__ double   g_sum[NBLK][2];   // [block][0=fg/thickness, 1=bg/separation]
__device__ unsigned g_cnt[NBLK][2];
__device__ unsigned g_ctr;

__global__ __launch_bounds__(TPB) void morph_all(const float* __restrict__ img,
                                                 const float* __restrict__ mask,
                                                 const float* __restrict__ tgt,
                                                 float* __restrict__ out) {
    __shared__ float    lut[1025];
    __shared__ unsigned Lpack[TPB];        // fwd dists at chunk's last row
    __shared__ unsigned Mpack[TPB];        // local bwd dists at chunk's row 0
    __shared__ double   wsum[4][2];
    __shared__ unsigned wcnt[4][2];
    __shared__ int      isLast;
    __shared__ double   fsum[4];
    __shared__ unsigned fcnt[4];

    const int tid   = threadIdx.x;
    const int b     = blockIdx.x;
    const int im    = b >> 7;                  // 0 = img, 1 = target
    const int cloc  = tid & (CPB - 1);
    const int chunk = tid >> 2;
    const int col   = ((b & 127) << 2) + cloc;
    const int rowBase = chunk * CH;

    const float* ps = (im ? tgt : img) + (size_t)rowBase * W + col;
    const float* pm = mask              + (size_t)rowBase * W + col;

    // ---- issue all global loads first (overlap DRAM latency with LUT fill) ----
    float xv[CH], mv[CH];
#pragma unroll
    for (int j = 0; j < CH; j++) { xv[j] = ps[j * W]; mv[j] = pm[j * W]; }

    for (int v = tid; v < 1025; v += TPB)
        lut[v] = (v == 1024) ? 1024.0f
                             : __fsqrt_rn((float)(v * v + (v & 1)) * 0.5f);

    // ---- phase 1: local forward scan, register state ----
    int      lf[CH];
    unsigned bbits = 0u, mbits = 0u;
    int dfg = 1024, dbg = 1024, p = CH;
    bool ph0 = false;
#pragma unroll
    for (int j = 0; j < CH; j++) {
        bool bb = xv[j] > 0.22f;
        bool mm = mv[j] > 0.5f;
        bbits |= bb ? (1u << j) : 0u;
        mbits |= mm ? (1u << j) : 0u;
        if (j == 0) ph0 = bb;
        else if (p == CH && bb != ph0) p = j;  // prefix-run length
        dfg = bb ? dfg + 1 : 0;
        dbg = bb ? 0 : dbg + 1;
        lf[j] = bb ? dfg : dbg;                // <= 1040, fits u16
    }
    int Mfg = ph0 ? ((p < CH) ? p : 1024) : 0; // analytic local-bwd at row 0
    int Mbg = ph0 ? 0 : ((p < CH) ? p : 1024);
    Lpack[tid] = ((unsigned)dfg << 16) | (unsigned)dbg;
    Mpack[tid] = ((unsigned)Mfg << 16) | (unsigned)Mbg;
    __syncthreads();

    // ---- carries across chunks (nearest-first, early-exit) ----
    int cfg = 1024, cbg = 1024;                // fwd carry-in at chunk start
    for (int m = chunk - 1; m >= 0; m--) {
        int off = CH * (chunk - 1 - m);
        if (off >= cfg && off >= cbg) break;   // later terms can't improve
        unsigned Lp = Lpack[m * CPB + cloc];
        cfg = min(cfg, (int)(Lp >> 16) + off);
        cbg = min(cbg, (int)(Lp & 0xFFFFu) + off);
    }
    cfg = min(cfg, 1024); cbg = min(cbg, 1024);
    int ufg = 1024, ubg = 1024;                // exact bwd dist at row rowBase+CH
    for (int m = chunk + 1; m < NCH; m++) {
        int off = CH * (m - chunk - 1);
        if (off >= ufg && off >= ubg) break;
        unsigned Mp = Mpack[m * CPB + cloc];
        ufg = min(ufg, (int)(Mp >> 16) + off);
        ubg = min(ubg, (int)(Mp & 0xFFFFu) + off);
    }
    ufg = min(ufg, 1024); ubg = min(ubg, 1024);

    // ---- phase 2: backward scan + combine + accumulate (registers only) ----
    float    sfg = 0.0f, sbg = 0.0f;
    unsigned nfg = 0u,   nbg = 0u;
#pragma unroll
    for (int j = CH - 1; j >= 0; j--) {
        bool bb = (bbits >> j) & 1u;
        ufg = bb ? ufg + 1 : 0;
        ubg = bb ? 0 : ubg + 1;
        int ef  = min(lf[j], (bb ? cfg : cbg) + j + 1);
        int eb  = bb ? ufg : ubg;
        int idx = min(min(ef, eb), 1024);
        float d = lut[idx];
        bool mm = (mbits >> j) & 1u;
        if (mm &&  bb) { sfg += d; nfg++; }
        if (mm && !bb) { sbg += d; nbg++; }
    }

    // ---- warp shfl reduction, then cross-warp ----
#pragma unroll
    for (int o = 16; o > 0; o >>= 1) {
        sfg += __shfl_down_sync(0xFFFFFFFFu, sfg, o);
        sbg += __shfl_down_sync(0xFFFFFFFFu, sbg, o);
        nfg += __shfl_down_sync(0xFFFFFFFFu, nfg, o);
        nbg += __shfl_down_sync(0xFFFFFFFFu, nbg, o);
    }
    const int wid = tid >> 5, lid = tid & 31;
    if (lid == 0) {
        wsum[wid][0] = (double)sfg;  wsum[wid][1] = (double)sbg;
        wcnt[wid][0] = nfg;          wcnt[wid][1] = nbg;
    }
    __syncthreads();
    if (tid == 0) {
        double   s0 = 0.0, s1 = 0.0;
        unsigned c0 = 0u,  c1 = 0u;
#pragma unroll
        for (int k = 0; k < 4; k++) {
            s0 += wsum[k][0];  s1 += wsum[k][1];
            c0 += wcnt[k][0];  c1 += wcnt[k][1];
        }
        g_sum[b][0] = s0;  g_sum[b][1] = s1;
        g_cnt[b][0] = c0;  g_cnt[b][1] = c1;
        __threadfence();
        isLast = (atomicAdd(&g_ctr, 1u) == NBLK - 1);
    }
    __syncthreads();

    // ---- last block: parallel deterministic final reduction + loss ----
    if (isLast) {
        {
            int ph = tid >> 5, ln = tid & 31;   // 4 phases x 32 lanes
            int base = (ph >> 1) * 128;         // blocks of that image
            int e    = ph & 1;
            double   s = 0.0;
            unsigned c = 0u;
#pragma unroll
            for (int t = 0; t < 4; t++) {
                int k = base + ln + 32 * t;
                s += g_sum[k][e];
                c += g_cnt[k][e];
            }
#pragma unroll
            for (int o = 16; o > 0; o >>= 1) {
                s += __shfl_down_sync(0xFFFFFFFFu, s, o);
                c += __shfl_down_sync(0xFFFFFFFFu, c, o);
            }
            if (ln == 0) { fsum[ph] = s; fcnt[ph] = c; }
        }
        __syncthreads();
        if (tid == 0) {
            const double VX2   = 21.0;          // 2 * VOXEL_SIZE
            const double TH_MU = 48.7578, TH_SD = 5.2874;
            const double SP_MU = 156.729, SP_SD = 46.1809;
            double n0 = fcnt[0] ? (double)fcnt[0] : 1.0;
            double n1 = fcnt[1] ? (double)fcnt[1] : 1.0;
            double n2 = fcnt[2] ? (double)fcnt[2] : 1.0;
            double n3 = fcnt[3] ? (double)fcnt[3] : 1.0;
            double tl = VX2 * fsum[0] / n0;     // thickness  (img)
            double sl = VX2 * fsum[1] / n1;     // separation (img)
            double th = VX2 * fsum[2] / n2;     // thickness  (tgt)
            double sh = VX2 * fsum[3] / n3;     // separation (tgt)
            double l1 = (tl - TH_MU) / TH_SD - (th - TH_MU) / TH_SD;
            double l7 = (sl - SP_MU) / SP_SD - (sh - SP_MU) / SP_SD;
            out[0] = (float)(0.5 * (l1 * l1 + l7 * l7));
            g_ctr = 0;                          // reset for next graph replay
        }
    }
}

extern "C" void kernel_launch(void* const* d_in, const int* in_sizes, int n_in,
                              void* d_out, int out_size) {
    const float* img  = (const float*)d_in[0];
    const float* mask = (const float*)d_in[1];
    const float* tgt  = (const float*)d_in[2];
    morph_all<<<NBLK, TPB>>>(img, mask, tgt, (float*)d_out);
}

// round 9
// speedup vs baseline: 1.4825x; 1.0925x over previous
#include <cuda_runtime.h>

#define W    512
#define CH   16           // rows per chunk
#define NCH  32           // chunks per column
#define CPB  8            // columns per block
#define TPB  256          // CPB * NCH
#define NBLK 128          // 2 images * (512 / CPB)
#define BIG  4096

__device__ double   g_sum[NBLK][2];   // [block][0=fg/thickness, 1=bg/separation]
__device__ unsigned g_cnt[NBLK][2];
__device__ unsigned g_ctr;

__global__ __launch_bounds__(TPB) void morph_all(const float* __restrict__ img,
                                                 const float* __restrict__ mask,
                                                 const float* __restrict__ tgt,
                                                 float* __restrict__ out) {
    __shared__ float    lut[1025];
    __shared__ unsigned Lpack[TPB];     // fwd dists at chunk's last row
    __shared__ unsigned Mpack[TPB];     // local bwd dists at chunk's row 0
    __shared__ double   wsum[8][2];
    __shared__ unsigned wcnt[8][2];
    __shared__ int      isLast;
    __shared__ double   fsum[4];
    __shared__ unsigned fcnt[4];

    const int tid   = threadIdx.x;
    const int b     = blockIdx.x;
    const int im    = b >> 6;                  // 0 = img, 1 = target
    const int cloc  = tid & (CPB - 1);
    const int chunk = tid / CPB;
    const int col   = ((b & 63) * CPB) + cloc;
    const int rowBase = chunk * CH;

    const float* ps = (im ? tgt : img) + (size_t)rowBase * W + col;
    const float* pm = mask              + (size_t)rowBase * W + col;

    // ---- loads -> bitmasks (ptxas batches the LDGs; huge MLP) ----
    unsigned bbits = 0u, mbits = 0u;
#pragma unroll
    for (int j = 0; j < CH; j++) {
        bbits |= (ps[j * W] > 0.22f) ? (1u << j) : 0u;
        mbits |= (pm[j * W] > 0.5f)  ? (1u << j) : 0u;
    }
    const unsigned Z = (~bbits) & 0xFFFFu;

    // chunk-boundary distances, all O(1) bit ops (no serial scan)
    int Lfg = Z     ? (__clz(Z)     - 16) : 1024;  // fwd fg-dist at last row
    int Lbg = bbits ? (__clz(bbits) - 16) : 1024;  // fwd bg-dist at last row
    int Mfg = Z     ? (__ffs(Z)     - 1)  : 1024;  // bwd fg-dist at row 0
    int Mbg = bbits ? (__ffs(bbits) - 1)  : 1024;  // bwd bg-dist at row 0
    Lpack[tid] = ((unsigned)Lfg << 16) | (unsigned)Lbg;
    Mpack[tid] = ((unsigned)Mfg << 16) | (unsigned)Mbg;

    for (int v = tid; v < 1025; v += TPB)
        lut[v] = (v == 1024) ? 1024.0f
                             : __fsqrt_rn((float)(v * v + (v & 1)) * 0.5f);
    __syncthreads();

    // ---- carries across chunks (nearest-first, early-exit) ----
    int cfg = 1024, cbg = 1024;                // exact fwd dist at row rowBase-1
    for (int m = chunk - 1; m >= 0; m--) {
        int off = CH * (chunk - 1 - m);
        if (off >= cfg && off >= cbg) break;
        unsigned Lp = Lpack[m * CPB + cloc];
        cfg = min(cfg, (int)(Lp >> 16) + off);
        cbg = min(cbg, (int)(Lp & 0xFFFFu) + off);
    }
    cfg = min(cfg, 1024); cbg = min(cbg, 1024);
    int ufg = 1024, ubg = 1024;                // exact bwd dist at row rowBase+CH
    for (int m = chunk + 1; m < NCH; m++) {
        int off = CH * (m - chunk - 1);
        if (off >= ufg && off >= ubg) break;
        unsigned Mp = Mpack[m * CPB + cloc];
        ufg = min(ufg, (int)(Mp >> 16) + off);
        ubg = min(ubg, (int)(Mp & 0xFFFFu) + off);
    }
    ufg = min(ufg, 1024); ubg = min(ubg, 1024);

    // ---- per-pixel distances: fully independent bit math (max ILP) ----
    float s0 = 0.0f, s1 = 0.0f, t0 = 0.0f, t1 = 0.0f;
#pragma unroll
    for (int j = 0; j < CH; j++) {
        bool     bb   = (bbits >> j) & 1u;
        unsigned opp  = bb ? Z : bbits;
        unsigned below = opp & ((1u << j) - 1u);
        unsigned above = opp & (0xFFFFFFFFu << (j + 1));
        int dn = below ? (j - 31 + __clz(below)) : BIG;   // nearest opp below
        int up = above ? (__ffs(above) - 1 - j)  : BIG;   // nearest opp above
        int fc = (bb ? cfg : cbg) + j + 1;                // via chunk start
        int bc = (bb ? ufg : ubg) + (CH - j);             // via chunk end
        int idx = min(min(dn, up), min(fc, bc));
        idx = min(idx, 1024);
        float d  = lut[idx];
        bool  mm = (mbits >> j) & 1u;
        float afg = (mm &&  bb) ? d : 0.0f;
        float abg = (mm && !bb) ? d : 0.0f;
        if (j & 1) { s1 += afg; t1 += abg; }
        else       { s0 += afg; t0 += abg; }
    }
    float    sfg = s0 + s1, sbg = t0 + t1;
    unsigned nfg = __popc(mbits & bbits);
    unsigned nbg = __popc(mbits & Z);

    // ---- warp shfl reduction, then cross-warp ----
#pragma unroll
    for (int o = 16; o > 0; o >>= 1) {
        sfg += __shfl_down_sync(0xFFFFFFFFu, sfg, o);
        sbg += __shfl_down_sync(0xFFFFFFFFu, sbg, o);
        nfg += __shfl_down_sync(0xFFFFFFFFu, nfg, o);
        nbg += __shfl_down_sync(0xFFFFFFFFu, nbg, o);
    }
    const int wid = tid >> 5, lid = tid & 31;
    if (lid == 0) {
        wsum[wid][0] = (double)sfg;  wsum[wid][1] = (double)sbg;
        wcnt[wid][0] = nfg;          wcnt[wid][1] = nbg;
    }
    __syncthreads();
    if (tid == 0) {
        double   a0 = 0.0, a1 = 0.0;
        unsigned c0 = 0u,  c1 = 0u;
#pragma unroll
        for (int k = 0; k < 8; k++) {
            a0 += wsum[k][0];  a1 += wsum[k][1];
            c0 += wcnt[k][0];  c1 += wcnt[k][1];
        }
        g_sum[b][0] = a0;  g_sum[b][1] = a1;
        g_cnt[b][0] = c0;  g_cnt[b][1] = c1;
        __threadfence();
        isLast = (atomicAdd(&g_ctr, 1u) == NBLK - 1);
    }
    __syncthreads();

    // ---- last block: parallel deterministic final reduction + loss ----
    if (isLast) {
        if (tid < 128) {
            int ph = tid >> 5, ln = tid & 31;   // 4 phases x 32 lanes
            int base = (ph >> 1) * 64;          // blocks of that image
            int e    = ph & 1;
            double   s = 0.0;
            unsigned c = 0u;
#pragma unroll
            for (int t = 0; t < 2; t++) {
                int k = base + ln + 32 * t;
                s += g_sum[k][e];
                c += g_cnt[k][e];
            }
#pragma unroll
            for (int o = 16; o > 0; o >>= 1) {
                s += __shfl_down_sync(0xFFFFFFFFu, s, o);
                c += __shfl_down_sync(0xFFFFFFFFu, c, o);
            }
            if (ln == 0) { fsum[ph] = s; fcnt[ph] = c; }
        }
        __syncthreads();
        if (tid == 0) {
            const double VX2   = 21.0;          // 2 * VOXEL_SIZE
            const double TH_MU = 48.7578, TH_SD = 5.2874;
            const double SP_MU = 156.729, SP_SD = 46.1809;
            double n0 = fcnt[0] ? (double)fcnt[0] : 1.0;
            double n1 = fcnt[1] ? (double)fcnt[1] : 1.0;
            double n2 = fcnt[2] ? (double)fcnt[2] : 1.0;
            double n3 = fcnt[3] ? (double)fcnt[3] : 1.0;
            double tl = VX2 * fsum[0] / n0;     // thickness  (img)
            double sl = VX2 * fsum[1] / n1;     // separation (img)
            double th = VX2 * fsum[2] / n2;     // thickness  (tgt)
            double sh = VX2 * fsum[3] / n3;     // separation (tgt)
            double l1 = (tl - TH_MU) / TH_SD - (th - TH_MU) / TH_SD;
            double l7 = (sl - SP_MU) / SP_SD - (sh - SP_MU) / SP_SD;
            out[0] = (float)(0.5 * (l1 * l1 + l7 * l7));
            g_ctr = 0;                          // reset for next graph replay
        }
    }
}

extern "C" void kernel_launch(void* const* d_in, const int* in_sizes, int n_in,
                              void* d_out, int out_size) {
    const float* img  = (const float*)d_in[0];
    const float* mask = (const float*)d_in[1];
    const float* tgt  = (const float*)d_in[2];
    morph_all<<<NBLK, TPB>>>(img, mask, tgt, (float*)d_out);
}